// round 16
// baseline (speedup 1.0000x reference)
#include <cuda_runtime.h>
#include <cuda_fp16.h>
#include <stdint.h>
#include <math.h>

#define T_SEQ   1024
#define D_MODEL 1024
#define NLAYER  4
#define FF_DIM  4096
#define VOCAB   32000
#define BT      2048
#define ATT_SCALE 0.125f

// ---------------- fp32 scratch ----------------------------------------------
__device__ float g_h   [BT * D_MODEL];
__device__ float g_n   [BT * D_MODEL];
__device__ float g_pred[BT * D_MODEL];
__device__ float g_corr[BT * D_MODEL];

// ---------------- activation scratch (fp16) ----------------------------------
__device__ __align__(16) __half g_qkvh[BT * 3 * D_MODEL];
__device__ __align__(16) __half g_qkvl[BT * 3 * D_MODEL];
__device__ __align__(16) __half g_a16[BT * D_MODEL];
__device__ __align__(16) __half g_d16[BT * D_MODEL];
__device__ __align__(16) __half g_p16[BT * D_MODEL];
__device__ __align__(16) __half g_c16[BT * D_MODEL];
__device__ __align__(16) __half g_g16[BT * D_MODEL];
__device__ __align__(16) __half g_f16[BT * FF_DIM];

// ---------------- weights (fp16 hi/lo; embed fp16 single) --------------------
#define SZ_WQKV (NLAYER * 2 * 3 * D_MODEL * D_MODEL)
#define SZ_WO   (NLAYER * D_MODEL * D_MODEL)
#define SZ_WG   (NLAYER * D_MODEL * 2 * D_MODEL)
#define SZ_W1   (NLAYER * FF_DIM * D_MODEL)
#define SZ_W2   (NLAYER * D_MODEL * FF_DIM)
#define SZ_EMB  (VOCAB * D_MODEL)
__device__ __align__(16) __half g_wqkv_h[SZ_WQKV], g_wqkv_l[SZ_WQKV];
__device__ __align__(16) __half g_wo_h  [SZ_WO],   g_wo_l  [SZ_WO];
__device__ __align__(16) __half g_wg_h  [SZ_WG],   g_wg_l  [SZ_WG];
__device__ __align__(16) __half g_w1_h  [SZ_W1],   g_w1_l  [SZ_W1];
__device__ __align__(16) __half g_w2_h  [SZ_W2],   g_w2_l  [SZ_W2];
__device__ __align__(16) __half g_embf  [SZ_EMB];

// ---------------- helpers ----------------------------------------------------
__device__ __forceinline__ uint32_t packh(float x, float y) {
    __half2 h = __floats2half2_rn(x, y);
    return *(uint32_t*)&h;
}
__device__ __forceinline__ uint32_t smem_u32(const void* p) {
    uint32_t a;
    asm("{ .reg .u64 t; cvta.to.shared.u64 t, %1; cvt.u32.u64 %0, t; }" : "=r"(a) : "l"(p));
    return a;
}
__device__ __forceinline__ void cp16(uint32_t s, const void* g) {
    asm volatile("cp.async.cg.shared.global [%0], [%1], 16;" :: "r"(s), "l"(g));
}
#define CP_COMMIT() asm volatile("cp.async.commit_group;" ::: "memory")
#define CP_WAIT0()  asm volatile("cp.async.wait_group 0;" ::: "memory")

__device__ __forceinline__ void ldmx4(uint32_t a, uint32_t& r0, uint32_t& r1,
                                      uint32_t& r2, uint32_t& r3) {
    asm volatile("ldmatrix.sync.aligned.m8n8.x4.shared.b16 {%0,%1,%2,%3}, [%4];"
                 : "=r"(r0), "=r"(r1), "=r"(r2), "=r"(r3) : "r"(a));
}
__device__ __forceinline__ void ldmx4t(uint32_t a, uint32_t& r0, uint32_t& r1,
                                       uint32_t& r2, uint32_t& r3) {
    asm volatile("ldmatrix.sync.aligned.m8n8.x4.trans.shared.b16 {%0,%1,%2,%3}, [%4];"
                 : "=r"(r0), "=r"(r1), "=r"(r2), "=r"(r3) : "r"(a));
}
__device__ __forceinline__ void mma16816h(float* d, const uint32_t* a, const uint32_t* b) {
    asm volatile("mma.sync.aligned.m16n8k16.row.col.f32.f16.f16.f32 "
                 "{%0,%1,%2,%3}, {%4,%5,%6,%7}, {%8,%9}, {%0,%1,%2,%3};"
                 : "+f"(d[0]), "+f"(d[1]), "+f"(d[2]), "+f"(d[3])
                 : "r"(a[0]), "r"(a[1]), "r"(a[2]), "r"(a[3]), "r"(b[0]), "r"(b[1]));
}

// ---------------- one-shot weight split (fp16 hi/lo; embed fp16) -------------
#define Q0 (SZ_WQKV/4)
#define Q1 (Q0 + SZ_WO/4)
#define Q2 (Q1 + SZ_WG/4)
#define Q3 (Q2 + SZ_W1/4)
#define Q4 (Q3 + SZ_W2/4)
#define Q5 (Q4 + SZ_EMB/4)
__global__ void split_all(
    const float4* w0, const float4* w1, const float4* w2,
    const float4* w3, const float4* w4, const float4* w5,
    uint2* h0, uint2* l0, uint2* h1, uint2* l1, uint2* h2, uint2* l2,
    uint2* h3, uint2* l3, uint2* h4, uint2* l4, uint2* f5)
{
    long i = (long)blockIdx.x * 256 + threadIdx.x;
    if (i >= Q5) return;
    const float4* src; uint2 *hi, *lo; long off; int single;
    if      (i < Q0) { src = w0; hi = h0; lo = l0; off = i;      single = 0; }
    else if (i < Q1) { src = w1; hi = h1; lo = l1; off = i - Q0; single = 0; }
    else if (i < Q2) { src = w2; hi = h2; lo = l2; off = i - Q1; single = 0; }
    else if (i < Q3) { src = w3; hi = h3; lo = l3; off = i - Q2; single = 0; }
    else if (i < Q4) { src = w4; hi = h4; lo = l4; off = i - Q3; single = 0; }
    else             { src = w5; hi = f5; lo = f5; off = i - Q4; single = 1; }
    float4 v = src[off];
    float vv[4] = {v.x, v.y, v.z, v.w};
    uint32_t Hw[2] = {0, 0}, Lw[2] = {0, 0};
    #pragma unroll
    for (int k = 0; k < 4; k++) {
        __half a = __float2half_rn(vv[k]);
        Hw[k >> 1] |= (uint32_t)__half_as_ushort(a) << ((k & 1) * 16);
        if (!single) {
            __half b = __float2half_rn(vv[k] - __half2float(a));
            Lw[k >> 1] |= (uint32_t)__half_as_ushort(b) << ((k & 1) * 16);
        }
    }
    hi[off] = make_uint2(Hw[0], Hw[1]);
    if (!single) lo[off] = make_uint2(Lw[0], Lw[1]);
}

// ---------------- gemm_hA: BN=128, KC=32, SROW=80, warp 32x64 (R11 config) ---
// Single A source. epi: 0 none, 2 gelu. Outputs: fp16 hi/lo pair or fp16.
#define SRA   80
#define A_ASZ (128 * SRA)
#define A_BSZ (128 * SRA)
#define A_STG (A_ASZ + 2 * A_BSZ)
#define GHA   (2 * A_STG)

__global__ __launch_bounds__(256, 2) void gemm_hA(
    const __half* __restrict__ A16,
    const __half* __restrict__ Wh, const __half* __restrict__ Wl,
    const float* __restrict__ bias,
    __half* __restrict__ Chh, __half* __restrict__ Chl, __half* __restrict__ C16,
    int M, int N, int K, int epi)
{
    extern __shared__ char smem[];
    uint32_t sb = smem_u32(smem);
    int tid = threadIdx.x, lane = tid & 31, w = tid >> 5;
    int wm = w & 3, wn = w >> 2;
    int bm = blockIdx.y * 128, bn = blockIdx.x * 128;

    float acc[2][8][4];
    #pragma unroll
    for (int i = 0; i < 2; i++)
        #pragma unroll
        for (int j = 0; j < 8; j++)
            #pragma unroll
            for (int e = 0; e < 4; e++) acc[i][j][e] = 0.f;

    int nk = K / 32;

    auto load_chunk = [&](int kc, uint32_t s) {
        int kb = kc * 32;
        #pragma unroll
        for (int it = 0; it < 6; it++) {
            int i = tid + it * 256;
            if (i < 512) {
                int row = i >> 2, c = i & 3;
                size_t go = (size_t)(bm + row) * K + kb + c * 8;
                cp16(s + row * SRA + c * 16, A16 + go);
            } else {
                int ii = i - 512;
                int hf = ii >= 512;
                int ww = ii & 511;
                int row = ww >> 2, c = ww & 3;
                size_t go = (size_t)(bn + row) * K + kb + c * 8;
                cp16(s + A_ASZ + (hf ? A_BSZ : 0) + row * SRA + c * 16, (hf ? Wl : Wh) + go);
            }
        }
    };

    load_chunk(0, sb);
    CP_COMMIT();

    for (int kc = 0; kc < nk; kc++) {
        CP_WAIT0();
        __syncthreads();
        if (kc + 1 < nk) { load_chunk(kc + 1, sb + ((kc + 1) & 1) * A_STG); CP_COMMIT(); }

        uint32_t s = sb + (kc & 1) * A_STG;
        #pragma unroll
        for (int t = 0; t < 2; t++) {
            uint32_t arow = wm * 32 + (lane & 15);
            uint32_t ak = (t * 16 + (lane >> 4) * 8) * 2;
            uint32_t ar[2][4];
            #pragma unroll
            for (int mg = 0; mg < 2; mg++) {
                uint32_t aoff = (arow + mg * 16) * SRA + ak;
                ldmx4(s + aoff, ar[mg][0], ar[mg][1], ar[mg][2], ar[mg][3]);
            }
            #pragma unroll
            for (int ng = 0; ng < 4; ng++) {
                uint32_t brow = wn * 64 + ng * 16 + (lane & 7) + ((lane >> 4) << 3);
                uint32_t boff = brow * SRA + (t * 16 + ((lane >> 3) & 1) * 8) * 2;
                uint32_t bh[4], bl[4];
                ldmx4(s + A_ASZ + boff,         bh[0], bh[1], bh[2], bh[3]);
                ldmx4(s + A_ASZ + A_BSZ + boff, bl[0], bl[1], bl[2], bl[3]);
                #pragma unroll
                for (int mg = 0; mg < 2; mg++) {
                    mma16816h(acc[mg][ng*2+0], ar[mg], &bh[0]);
                    mma16816h(acc[mg][ng*2+1], ar[mg], &bh[2]);
                    mma16816h(acc[mg][ng*2+0], ar[mg], &bl[0]);
                    mma16816h(acc[mg][ng*2+1], ar[mg], &bl[2]);
                }
            }
        }
    }

    #pragma unroll
    for (int mg = 0; mg < 2; mg++) {
        #pragma unroll
        for (int j = 0; j < 8; j++) {
            int m0 = bm + wm * 32 + mg * 16 + (lane >> 2);
            int n0 = bn + wn * 64 + j * 8 + (lane & 3) * 2;
            #pragma unroll
            for (int e = 0; e < 4; e++) {
                int m = m0 + (e >> 1) * 8;
                int n = n0 + (e & 1);
                size_t idx = (size_t)m * N + n;
                float v = acc[mg][j][e];
                if (bias) v += bias[n];
                if (epi == 2) v = 0.5f * v * (1.f + erff(v * 0.70710678118f));
                if (Chh) {
                    __half a = __float2half_rn(v);
                    Chh[idx] = a;
                    Chl[idx] = __float2half_rn(v - __half2float(a));
                }
                if (C16) C16[idx] = __float2half_rn(v);
            }
        }
    }
}

// ---------------- gemm_hB: BN=64, KC=64, SR=144, warp 32x32 (R14 config) -----
// Dual-A concat at kSplit. epi: 1 +res, 3 gated. Outputs: fp32 or fp16.
#define SRB   144
#define B_ASZ (128 * SRB)
#define B_BSZ (64 * SRB)
#define B_STG (B_ASZ + 2 * B_BSZ)
#define GHB   (2 * B_STG)

__global__ __launch_bounds__(256, 2) void gemm_hB(
    const __half* __restrict__ A16, const __half* __restrict__ A16b,
    int kSplit, int lda1, int lda2,
    const __half* __restrict__ Wh, const __half* __restrict__ Wl,
    const float* __restrict__ bias, const float* __restrict__ res,
    const float* __restrict__ corr,
    float* __restrict__ Cf, __half* __restrict__ C16,
    int M, int N, int K, int epi)
{
    extern __shared__ char smem[];
    uint32_t sb = smem_u32(smem);
    int tid = threadIdx.x, lane = tid & 31, w = tid >> 5;
    int wm = w & 3, wn = w >> 2;
    int bm = blockIdx.y * 128, bn = blockIdx.x * 64;

    float acc[2][4][4];
    #pragma unroll
    for (int i = 0; i < 2; i++)
        #pragma unroll
        for (int j = 0; j < 4; j++)
            #pragma unroll
            for (int e = 0; e < 4; e++) acc[i][j][e] = 0.f;

    int nk = K / 64;

    auto load_chunk = [&](int kc, uint32_t s) {
        int kb = kc * 64;
        const __half* sA; int lda, koff;
        if (kb < kSplit) { sA = A16;  lda = lda1; koff = kb; }
        else             { sA = A16b; lda = lda2; koff = kb - kSplit; }
        #pragma unroll
        for (int it = 0; it < 8; it++) {
            int i = tid + it * 256;
            if (i < 1024) {
                int row = i >> 3, c = i & 7;
                size_t go = (size_t)(bm + row) * lda + koff + c * 8;
                cp16(s + row * SRB + c * 16, sA + go);
            } else {
                int ii = i - 1024;
                int hf = ii >= 512;
                int ww = ii & 511;
                int row = ww >> 3, c = ww & 7;
                size_t go = (size_t)(bn + row) * K + kb + c * 8;
                cp16(s + B_ASZ + (hf ? B_BSZ : 0) + row * SRB + c * 16, (hf ? Wl : Wh) + go);
            }
        }
    };

    load_chunk(0, sb);
    CP_COMMIT();

    for (int kc = 0; kc < nk; kc++) {
        CP_WAIT0();
        __syncthreads();
        if (kc + 1 < nk) { load_chunk(kc + 1, sb + ((kc + 1) & 1) * B_STG); CP_COMMIT(); }

        uint32_t s = sb + (kc & 1) * B_STG;
        #pragma unroll
        for (int t = 0; t < 4; t++) {
            uint32_t arow = wm * 32 + (lane & 15);
            uint32_t ak = (t * 16 + (lane >> 4) * 8) * 2;
            uint32_t ar[2][4];
            #pragma unroll
            for (int mg = 0; mg < 2; mg++) {
                uint32_t aoff = (arow + mg * 16) * SRB + ak;
                ldmx4(s + aoff, ar[mg][0], ar[mg][1], ar[mg][2], ar[mg][3]);
            }
            #pragma unroll
            for (int ng = 0; ng < 2; ng++) {
                uint32_t brow = wn * 32 + ng * 16 + (lane & 7) + ((lane >> 4) << 3);
                uint32_t boff = brow * SRB + (t * 16 + ((lane >> 3) & 1) * 8) * 2;
                uint32_t bh[4], bl[4];
                ldmx4(s + B_ASZ + boff,         bh[0], bh[1], bh[2], bh[3]);
                ldmx4(s + B_ASZ + B_BSZ + boff, bl[0], bl[1], bl[2], bl[3]);
                #pragma unroll
                for (int mg = 0; mg < 2; mg++) {
                    mma16816h(acc[mg][ng*2+0], ar[mg], &bh[0]);
                    mma16816h(acc[mg][ng*2+1], ar[mg], &bh[2]);
                    mma16816h(acc[mg][ng*2+0], ar[mg], &bl[0]);
                    mma16816h(acc[mg][ng*2+1], ar[mg], &bl[2]);
                }
            }
        }
    }

    #pragma unroll
    for (int mg = 0; mg < 2; mg++) {
        #pragma unroll
        for (int j = 0; j < 4; j++) {
            int m0 = bm + wm * 32 + mg * 16 + (lane >> 2);
            int n0 = bn + wn * 32 + j * 8 + (lane & 3) * 2;
            #pragma unroll
            for (int e = 0; e < 4; e++) {
                int m = m0 + (e >> 1) * 8;
                int n = n0 + (e & 1);
                size_t idx = (size_t)m * N + n;
                float v = acc[mg][j][e];
                if (bias) v += bias[n];
                if (epi == 1)      v += res[idx];
                else if (epi == 3) v = res[idx] + corr[idx] / (1.f + __expf(-v));
                if (Cf) Cf[idx] = v;
                if (C16) C16[idx] = __float2half_rn(v);
            }
        }
    }
}

// ---------------- logits GEMM (fp16 1-mma, 128x64, KC=64) --------------------
#define FB    (128 * SRB)
#define FSTG  (FB + 64 * SRB)
#define FSMEM (2 * FSTG)

__global__ __launch_bounds__(256, 3) void gemm_f16(
    const __half* __restrict__ Ah, const __half* __restrict__ Wh,
    float* __restrict__ Cf, int M, int N, int K)
{
    extern __shared__ char smem[];
    uint32_t sb = smem_u32(smem);
    int tid = threadIdx.x, lane = tid & 31, w = tid >> 5;
    int wm = w & 3, wn = w >> 2;
    int bm = blockIdx.y * 128, bn = blockIdx.x * 64;

    float acc[2][4][4];
    #pragma unroll
    for (int i = 0; i < 2; i++)
        #pragma unroll
        for (int j = 0; j < 4; j++)
            #pragma unroll
            for (int e = 0; e < 4; e++) acc[i][j][e] = 0.f;

    int nk = K / 64;

    auto load_chunk = [&](int kc, uint32_t s) {
        int kb = kc * 64;
        #pragma unroll
        for (int it = 0; it < 6; it++) {
            int i = tid + it * 256;
            if (i < 1024) {
                int row = i >> 3, c = i & 7;
                size_t go = (size_t)(bm + row) * K + kb + c * 8;
                cp16(s + row * SRB + c * 16, Ah + go);
            } else {
                int ii = i - 1024;
                int row = ii >> 3, c = ii & 7;
                size_t go = (size_t)(bn + row) * K + kb + c * 8;
                cp16(s + FB + row * SRB + c * 16, Wh + go);
            }
        }
    };

    load_chunk(0, sb);
    CP_COMMIT();

    for (int kc = 0; kc < nk; kc++) {
        CP_WAIT0();
        __syncthreads();
        if (kc + 1 < nk) { load_chunk(kc + 1, sb + ((kc + 1) & 1) * FSTG); CP_COMMIT(); }

        uint32_t s = sb + (kc & 1) * FSTG;
        #pragma unroll
        for (int t = 0; t < 4; t++) {
            uint32_t arow = wm * 32 + (lane & 15);
            uint32_t ak = (t * 16 + (lane >> 4) * 8) * 2;
            uint32_t ahr[2][4];
            #pragma unroll
            for (int mg = 0; mg < 2; mg++) {
                uint32_t aoff = (arow + mg * 16) * SRB + ak;
                ldmx4(s + aoff, ahr[mg][0], ahr[mg][1], ahr[mg][2], ahr[mg][3]);
            }
            #pragma unroll
            for (int ng = 0; ng < 2; ng++) {
                uint32_t brow = wn * 32 + ng * 16 + (lane & 7) + ((lane >> 4) << 3);
                uint32_t boff = brow * SRB + (t * 16 + ((lane >> 3) & 1) * 8) * 2;
                uint32_t bw[4];
                ldmx4(s + FB + boff, bw[0], bw[1], bw[2], bw[3]);
                #pragma unroll
                for (int mg = 0; mg < 2; mg++) {
                    mma16816h(acc[mg][ng*2+0], ahr[mg], &bw[0]);
                    mma16816h(acc[mg][ng*2+1], ahr[mg], &bw[2]);
                }
            }
        }
    }

    #pragma unroll
    for (int mg = 0; mg < 2; mg++) {
        #pragma unroll
        for (int j = 0; j < 4; j++) {
            int m0 = bm + wm * 32 + mg * 16 + (lane >> 2);
            int n0 = bn + wn * 32 + j * 8 + (lane & 3) * 2;
            #pragma unroll
            for (int e = 0; e < 4; e++) {
                int m = m0 + (e >> 1) * 8;
                int n = n0 + (e & 1);
                Cf[(size_t)m * N + n] = acc[mg][j][e];
            }
        }
    }
}

// ---------------- embedding ------------------------------------------------
__global__ void embed_kernel(const int* __restrict__ x, const float* __restrict__ emb,
                             const float* __restrict__ pos, float* __restrict__ h) {
    int row = blockIdx.x;
    int t   = row & (T_SEQ - 1);
    int tok = x[row];
    const float* e = emb + (size_t)tok * D_MODEL;
    const float* p = pos + (size_t)t   * D_MODEL;
    float* o = h + (size_t)row * D_MODEL;
    for (int d = threadIdx.x; d < D_MODEL; d += blockDim.x)
        o[d] = e[d] + p[d];
}

// ---------------- layernorm -------------------------------------------------
__global__ void ln_kernel(const float* __restrict__ in, const float* __restrict__ g,
                          const float* __restrict__ b, float* __restrict__ of,
                          __half* __restrict__ o16) {
    int row = blockIdx.x;
    const float* x = in + (size_t)row * D_MODEL;
    int tid = threadIdx.x;
    float s = 0.f, ss = 0.f;
    for (int d = tid; d < D_MODEL; d += 256) { float v = x[d]; s += v; ss += v * v; }
    #pragma unroll
    for (int off = 16; off; off >>= 1) {
        s  += __shfl_xor_sync(0xffffffffu, s,  off);
        ss += __shfl_xor_sync(0xffffffffu, ss, off);
    }
    __shared__ float shs[8], shss[8];
    if ((tid & 31) == 0) { shs[tid >> 5] = s; shss[tid >> 5] = ss; }
    __syncthreads();
    float tots = 0.f, totss = 0.f;
    #pragma unroll
    for (int i = 0; i < 8; i++) { tots += shs[i]; totss += shss[i]; }
    float mean = tots * (1.f / D_MODEL);
    float var  = totss * (1.f / D_MODEL) - mean * mean;
    float rstd = rsqrtf(var + 1e-5f);
    for (int d = tid; d < D_MODEL; d += 256) {
        float v = (x[d] - mean) * rstd * g[d] + b[d];
        size_t idx = (size_t)row * D_MODEL + d;
        if (of) of[idx] = v;
        o16[idx] = __float2half_rn(v);
    }
}

// ---------------- HMMA flash attention (fp16, Q/P single, K/V hi-lo) ---------
#define AT_ROWB   144
#define AT_Q      0
#define AT_STAGE0 9216
#define AT_STGSZ  36864
#define AT_KH     0
#define AT_KL     9216
#define AT_VH     18432
#define AT_VL     27648
#define AT_SMEM   (9216 + 2 * 36864)

__global__ __launch_bounds__(128, 2) void attn_mma(
    const __half* __restrict__ qkvh, const __half* __restrict__ qkvl,
    const float* __restrict__ nIn,
    float* __restrict__ outF, __half* __restrict__ o16, __half* __restrict__ d16)
{
    extern __shared__ char sm[];
    uint32_t sb = smem_u32(sm);
    int qt = blockIdx.x, hh = blockIdx.y, b = blockIdx.z;
    int tid = threadIdx.x, lane = tid & 31, wq = tid >> 5;
    int qb = wq * 16;

    #pragma unroll
    for (int it = 0; it < 4; it++) {
        int i = tid + it * 128;
        int row = i >> 3, c = i & 7;
        size_t ge = (size_t)(b * T_SEQ + qt * 64 + row) * 3072 + hh * 64 + c * 8;
        cp16(sb + AT_Q + row * AT_ROWB + c * 16, qkvh + ge);
    }

    auto load_kv = [&](int kt, int stage) {
        uint32_t stb = sb + AT_STAGE0 + stage * AT_STGSZ;
        #pragma unroll
        for (int it = 0; it < 16; it++) {
            int i = tid + it * 128;
            int tensor = i >> 9, ww = i & 511, row = ww >> 3, c = ww & 7;
            int kvoff = (tensor >= 2) ? 2048 : 1024;
            size_t ge = (size_t)(b * T_SEQ + kt * 64 + row) * 3072 + kvoff + hh * 64 + c * 8;
            const __half* src = (tensor & 1) ? qkvl : qkvh;
            uint32_t toff = tensor * 9216;
            cp16(stb + toff + row * AT_ROWB + c * 16, src + ge);
        }
    };
    load_kv(0, 0);
    CP_COMMIT();

    float O[8][4];
    #pragma unroll
    for (int j = 0; j < 8; j++)
        #pragma unroll
        for (int e = 0; e < 4; e++) O[j][e] = 0.f;
    float m0 = -1e30f, m1 = -1e30f, l0 = 0.f, l1 = 0.f;

    int r0 = qt * 64 + qb + (lane >> 2);
    int r1 = r0 + 8;

    for (int kt = 0; kt <= qt; kt++) {
        CP_WAIT0();
        __syncthreads();
        if (kt < qt) { load_kv(kt + 1, (kt + 1) & 1); CP_COMMIT(); }

        uint32_t stb = sb + AT_STAGE0 + (kt & 1) * AT_STGSZ;

        float S[8][4];
        #pragma unroll
        for (int j = 0; j < 8; j++)
            #pragma unroll
            for (int e = 0; e < 4; e++) S[j][e] = 0.f;

        #pragma unroll
        for (int t = 0; t < 4; t++) {
            uint32_t qa = sb + AT_Q + (qb + (lane & 15)) * AT_ROWB + (t * 16 + (lane >> 4) * 8) * 2;
            uint32_t q[4];
            ldmx4(qa, q[0], q[1], q[2], q[3]);
            #pragma unroll
            for (int jj = 0; jj < 4; jj++) {
                uint32_t ka = stb + (jj * 16 + (lane & 7) + ((lane >> 4) << 3)) * AT_ROWB
                            + (t * 16 + ((lane >> 3) & 1) * 8) * 2;
                uint32_t kh[4], kl[4];
                ldmx4(ka + AT_KH, kh[0], kh[1], kh[2], kh[3]);
                ldmx4(ka + AT_KL, kl[0], kl[1], kl[2], kl[3]);
                mma16816h(S[jj*2+0], q, &kh[0]); mma16816h(S[jj*2+1], q, &kh[2]);
                mma16816h(S[jj*2+0], q, &kl[0]); mma16816h(S[jj*2+1], q, &kl[2]);
            }
        }

        int cb = kt * 64 + ((lane & 3) << 1);
        float mx0 = -1e30f, mx1 = -1e30f;
        #pragma unroll
        for (int j = 0; j < 8; j++) {
            int c0 = cb + j * 8, c1 = c0 + 1;
            float v;
            v = (c0 <= r0) ? S[j][0] * ATT_SCALE : -1e30f; S[j][0] = v; mx0 = fmaxf(mx0, v);
            v = (c1 <= r0) ? S[j][1] * ATT_SCALE : -1e30f; S[j][1] = v; mx0 = fmaxf(mx0, v);
            v = (c0 <= r1) ? S[j][2] * ATT_SCALE : -1e30f; S[j][2] = v; mx1 = fmaxf(mx1, v);
            v = (c1 <= r1) ? S[j][3] * ATT_SCALE : -1e30f; S[j][3] = v; mx1 = fmaxf(mx1, v);
        }
        mx0 = fmaxf(mx0, __shfl_xor_sync(0xffffffffu, mx0, 1));
        mx0 = fmaxf(mx0, __shfl_xor_sync(0xffffffffu, mx0, 2));
        mx1 = fmaxf(mx1, __shfl_xor_sync(0xffffffffu, mx1, 1));
        mx1 = fmaxf(mx1, __shfl_xor_sync(0xffffffffu, mx1, 2));
        float mn0 = fmaxf(m0, mx0), mn1 = fmaxf(m1, mx1);
        float a0 = __expf(m0 - mn0), a1 = __expf(m1 - mn1);
        m0 = mn0; m1 = mn1;
        float s0 = 0.f, s1 = 0.f;
        #pragma unroll
        for (int j = 0; j < 8; j++) {
            S[j][0] = __expf(S[j][0] - m0); s0 += S[j][0];
            S[j][1] = __expf(S[j][1] - m0); s0 += S[j][1];
            S[j][2] = __expf(S[j][2] - m1); s1 += S[j][2];
            S[j][3] = __expf(S[j][3] - m1); s1 += S[j][3];
        }
        s0 += __shfl_xor_sync(0xffffffffu, s0, 1);
        s0 += __shfl_xor_sync(0xffffffffu, s0, 2);
        s1 += __shfl_xor_sync(0xffffffffu, s1, 1);
        s1 += __shfl_xor_sync(0xffffffffu, s1, 2);
        l0 = l0 * a0 + s0; l1 = l1 * a1 + s1;
        #pragma unroll
        for (int j = 0; j < 8; j++) {
            O[j][0] *= a0; O[j][1] *= a0; O[j][2] *= a1; O[j][3] *= a1;
        }

        #pragma unroll
        for (int t = 0; t < 4; t++) {
            uint32_t pa[4];
            pa[0] = packh(S[2*t  ][0], S[2*t  ][1]);
            pa[1] = packh(S[2*t  ][2], S[2*t  ][3]);
            pa[2] = packh(S[2*t+1][0], S[2*t+1][1]);
            pa[3] = packh(S[2*t+1][2], S[2*t+1][3]);
            #pragma unroll
            for (int dd = 0; dd < 4; dd++) {
                uint32_t va = stb + (t * 16 + (lane & 7) + ((lane >> 3) & 1) * 8) * AT_ROWB
                            + (dd * 16 + (lane >> 4) * 8) * 2;
                uint32_t vh[4], vl[4];
                ldmx4t(va + AT_VH, vh[0], vh[1], vh[2], vh[3]);
                ldmx4t(va + AT_VL, vl[0], vl[1], vl[2], vl[3]);
                mma16816h(O[dd*2+0], pa, &vh[0]); mma16816h(O[dd*2+1], pa, &vh[2]);
                mma16816h(O[dd*2+0], pa, &vl[0]); mma16816h(O[dd*2+1], pa, &vl[2]);
            }
        }
    }

    float i0 = 1.f / l0, i1 = 1.f / l1;
    int tok0 = b * T_SEQ + r0, tok1 = b * T_SEQ + r1;
    #pragma unroll
    for (int j = 0; j < 8; j++) {
        int d = hh * 64 + j * 8 + ((lane & 3) << 1);
        size_t idx0 = (size_t)tok0 * D_MODEL + d;
        size_t idx1 = (size_t)tok1 * D_MODEL + d;
        float v00 = O[j][0] * i0, v01 = O[j][1] * i0;
        float v10 = O[j][2] * i1, v11 = O[j][3] * i1;
        outF[idx0] = v00; outF[idx0 + 1] = v01;
        outF[idx1] = v10; outF[idx1 + 1] = v11;
        o16[idx0]     = __float2half_rn(v00);
        o16[idx0 + 1] = __float2half_rn(v01);
        o16[idx1]     = __float2half_rn(v10);
        o16[idx1 + 1] = __float2half_rn(v11);
        if (d16) {
            d16[idx0]     = __float2half_rn(nIn[idx0]     - v00);
            d16[idx0 + 1] = __float2half_rn(nIn[idx0 + 1] - v01);
            d16[idx1]     = __float2half_rn(nIn[idx1]     - v10);
            d16[idx1 + 1] = __float2half_rn(nIn[idx1 + 1] - v11);
        }
    }
}

// ---------------- driver ----------------------------------------------------
extern "C" void kernel_launch(void* const* d_in, const int* in_sizes, int n_in,
                              void* d_out, int out_size) {
    const int*   x      = (const int*)  d_in[0];
    const float* embed  = (const float*)d_in[1];
    const float* pos    = (const float*)d_in[2];
    const float* Wqkv   = (const float*)d_in[3];
    const float* bqkv   = (const float*)d_in[4];
    const float* Wo     = (const float*)d_in[5];
    const float* bo     = (const float*)d_in[6];
    const float* Wg     = (const float*)d_in[7];
    const float* bg     = (const float*)d_in[8];
    const float* ln1_g  = (const float*)d_in[9];
    const float* ln1_b  = (const float*)d_in[10];
    const float* W1     = (const float*)d_in[11];
    const float* b1     = (const float*)d_in[12];
    const float* W2     = (const float*)d_in[13];
    const float* b2     = (const float*)d_in[14];
    const float* ln2_g  = (const float*)d_in[15];
    const float* ln2_b  = (const float*)d_in[16];
    const float* lnf_g  = (const float*)d_in[17];
    const float* lnf_b  = (const float*)d_in[18];
    float* out = (float*)d_out;

    cudaFuncSetAttribute(gemm_hA,  cudaFuncAttributeMaxDynamicSharedMemorySize, GHA);
    cudaFuncSetAttribute(gemm_hB,  cudaFuncAttributeMaxDynamicSharedMemorySize, GHB);
    cudaFuncSetAttribute(gemm_f16, cudaFuncAttributeMaxDynamicSharedMemorySize, FSMEM);
    cudaFuncSetAttribute(attn_mma, cudaFuncAttributeMaxDynamicSharedMemorySize, AT_SMEM);

    float *h, *n, *pred, *corr;
    cudaGetSymbolAddress((void**)&h,    g_h);
    cudaGetSymbolAddress((void**)&n,    g_n);
    cudaGetSymbolAddress((void**)&pred, g_pred);
    cudaGetSymbolAddress((void**)&corr, g_corr);
    __half *qh, *ql, *a16, *d16, *p16, *c16, *gg16, *f16, *embf;
    cudaGetSymbolAddress((void**)&qh,   g_qkvh);
    cudaGetSymbolAddress((void**)&ql,   g_qkvl);
    cudaGetSymbolAddress((void**)&a16,  g_a16);
    cudaGetSymbolAddress((void**)&d16,  g_d16);
    cudaGetSymbolAddress((void**)&p16,  g_p16);
    cudaGetSymbolAddress((void**)&c16,  g_c16);
    cudaGetSymbolAddress((void**)&gg16, g_g16);
    cudaGetSymbolAddress((void**)&f16,  g_f16);
    cudaGetSymbolAddress((void**)&embf, g_embf);
    __half *wqkv_h, *wqkv_l, *wo_h, *wo_l, *wg_h, *wg_l, *w1_h, *w1_l, *w2_h, *w2_l;
    cudaGetSymbolAddress((void**)&wqkv_h, g_wqkv_h); cudaGetSymbolAddress((void**)&wqkv_l, g_wqkv_l);
    cudaGetSymbolAddress((void**)&wo_h,   g_wo_h);   cudaGetSymbolAddress((void**)&wo_l,   g_wo_l);
    cudaGetSymbolAddress((void**)&wg_h,   g_wg_h);   cudaGetSymbolAddress((void**)&wg_l,   g_wg_l);
    cudaGetSymbolAddress((void**)&w1_h,   g_w1_h);   cudaGetSymbolAddress((void**)&w1_l,   g_w1_l);
    cudaGetSymbolAddress((void**)&w2_h,   g_w2_h);   cudaGetSymbolAddress((void**)&w2_l,   g_w2_l);

    split_all<<<(int)((Q5 + 255) / 256), 256>>>(
        (const float4*)Wqkv, (const float4*)Wo, (const float4*)Wg,
        (const float4*)W1, (const float4*)W2, (const float4*)embed,
        (uint2*)wqkv_h, (uint2*)wqkv_l, (uint2*)wo_h, (uint2*)wo_l,
        (uint2*)wg_h, (uint2*)wg_l, (uint2*)w1_h, (uint2*)w1_l,
        (uint2*)w2_h, (uint2*)w2_l, (uint2*)embf);

    dim3 attng(T_SEQ / 64, 16, 2);

    embed_kernel<<<BT, 256>>>(x, embed, pos, h);

    for (int l = 0; l < NLAYER; l++) {
        ln_kernel<<<BT, 256>>>(h, ln1_g + l * D_MODEL, ln1_b + l * D_MODEL, n, a16);
        // qkv1 (BN=128, R11 config)
        gemm_hA<<<dim3(3072/128, BT/128), 256, GHA>>>(
            a16, wqkv_h + (size_t)(l*2+0)*3072*D_MODEL, wqkv_l + (size_t)(l*2+0)*3072*D_MODEL,
            bqkv + (l*2+0)*3072, qh, ql, nullptr, BT, 3072, D_MODEL, 0);
        attn_mma<<<attng, 128, AT_SMEM>>>(qh, ql, n, pred, p16, d16);
        // qkv2
        gemm_hA<<<dim3(3072/128, BT/128), 256, GHA>>>(
            d16, wqkv_h + (size_t)(l*2+1)*3072*D_MODEL, wqkv_l + (size_t)(l*2+1)*3072*D_MODEL,
            bqkv + (l*2+1)*3072, qh, ql, nullptr, BT, 3072, D_MODEL, 0);
        attn_mma<<<attng, 128, AT_SMEM>>>(qh, ql, nullptr, corr, c16, nullptr);
        // gate (BN=64, dual-A, R14 config)
        gemm_hB<<<dim3(D_MODEL/64, BT/128), 256, GHB>>>(
            p16, c16, D_MODEL, D_MODEL, D_MODEL,
            wg_h + (size_t)l*D_MODEL*2*D_MODEL, wg_l + (size_t)l*D_MODEL*2*D_MODEL,
            bg + l*D_MODEL, pred, corr,
            nullptr, gg16, BT, D_MODEL, 2*D_MODEL, 3);
        // Wo
        gemm_hB<<<dim3(D_MODEL/64, BT/128), 256, GHB>>>(
            gg16, nullptr, 1 << 30, D_MODEL, 0,
            wo_h + (size_t)l*D_MODEL*D_MODEL, wo_l + (size_t)l*D_MODEL*D_MODEL,
            bo + l*D_MODEL, h, nullptr,
            h, nullptr, BT, D_MODEL, D_MODEL, 1);
        // FF
        ln_kernel<<<BT, 256>>>(h, ln2_g + l * D_MODEL, ln2_b + l * D_MODEL, nullptr, a16);
        gemm_hA<<<dim3(FF_DIM/128, BT/128), 256, GHA>>>(
            a16, w1_h + (size_t)l*FF_DIM*D_MODEL, w1_l + (size_t)l*FF_DIM*D_MODEL,
            b1 + l*FF_DIM, nullptr, nullptr, f16, BT, FF_DIM, D_MODEL, 2);
        gemm_hB<<<dim3(D_MODEL/64, BT/128), 256, GHB>>>(
            f16, nullptr, 1 << 30, FF_DIM, 0,
            w2_h + (size_t)l*D_MODEL*FF_DIM, w2_l + (size_t)l*D_MODEL*FF_DIM,
            b2 + l*D_MODEL, h, nullptr,
            h, nullptr, BT, D_MODEL, FF_DIM, 1);
    }

    ln_kernel<<<BT, 256>>>(h, lnf_g, lnf_b, nullptr, a16);
    gemm_f16<<<dim3(VOCAB/64, BT/128), 256, FSMEM>>>(
        a16, embf, out, BT, VOCAB, D_MODEL);
}

// round 17
// speedup vs baseline: 1.5239x; 1.5239x over previous
#include <cuda_runtime.h>
#include <cuda_fp16.h>
#include <stdint.h>
#include <math.h>

#define T_SEQ   1024
#define D_MODEL 1024
#define NLAYER  4
#define FF_DIM  4096
#define VOCAB   32000
#define BT      2048
#define ATT_SCALE 0.125f

// ---------------- fp32 scratch ----------------------------------------------
__device__ float g_h   [BT * D_MODEL];
__device__ float g_n   [BT * D_MODEL];
__device__ float g_pred[BT * D_MODEL];
__device__ float g_corr[BT * D_MODEL];

// ---------------- activation scratch (fp16) ----------------------------------
__device__ __align__(16) __half g_qkvh[BT * 3 * D_MODEL];
__device__ __align__(16) __half g_qkvl[BT * 3 * D_MODEL];
__device__ __align__(16) __half g_a16[BT * D_MODEL];
__device__ __align__(16) __half g_d16[BT * D_MODEL];
__device__ __align__(16) __half g_p16[BT * D_MODEL];
__device__ __align__(16) __half g_c16[BT * D_MODEL];
__device__ __align__(16) __half g_g16[BT * D_MODEL];
__device__ __align__(16) __half g_f16[BT * FF_DIM];

// ---------------- weights (fp16 hi/lo; embed fp16 single) --------------------
#define SZ_WQKV (NLAYER * 2 * 3 * D_MODEL * D_MODEL)
#define SZ_WO   (NLAYER * D_MODEL * D_MODEL)
#define SZ_WG   (NLAYER * D_MODEL * 2 * D_MODEL)
#define SZ_W1   (NLAYER * FF_DIM * D_MODEL)
#define SZ_W2   (NLAYER * D_MODEL * FF_DIM)
#define SZ_EMB  (VOCAB * D_MODEL)
__device__ __align__(16) __half g_wqkv_h[SZ_WQKV], g_wqkv_l[SZ_WQKV];
__device__ __align__(16) __half g_wo_h  [SZ_WO],   g_wo_l  [SZ_WO];
__device__ __align__(16) __half g_wg_h  [SZ_WG],   g_wg_l  [SZ_WG];
__device__ __align__(16) __half g_w1_h  [SZ_W1],   g_w1_l  [SZ_W1];
__device__ __align__(16) __half g_w2_h  [SZ_W2],   g_w2_l  [SZ_W2];
__device__ __align__(16) __half g_embf  [SZ_EMB];

// ---------------- helpers ----------------------------------------------------
__device__ __forceinline__ uint32_t packh(float x, float y) {
    __half2 h = __floats2half2_rn(x, y);
    return *(uint32_t*)&h;
}
__device__ __forceinline__ uint32_t smem_u32(const void* p) {
    uint32_t a;
    asm("{ .reg .u64 t; cvta.to.shared.u64 t, %1; cvt.u32.u64 %0, t; }" : "=r"(a) : "l"(p));
    return a;
}
__device__ __forceinline__ void cp16(uint32_t s, const void* g) {
    asm volatile("cp.async.cg.shared.global [%0], [%1], 16;" :: "r"(s), "l"(g));
}
#define CP_COMMIT() asm volatile("cp.async.commit_group;" ::: "memory")
#define CP_WAIT0()  asm volatile("cp.async.wait_group 0;" ::: "memory")

__device__ __forceinline__ void ldmx4(uint32_t a, uint32_t& r0, uint32_t& r1,
                                      uint32_t& r2, uint32_t& r3) {
    asm volatile("ldmatrix.sync.aligned.m8n8.x4.shared.b16 {%0,%1,%2,%3}, [%4];"
                 : "=r"(r0), "=r"(r1), "=r"(r2), "=r"(r3) : "r"(a));
}
__device__ __forceinline__ void ldmx4t(uint32_t a, uint32_t& r0, uint32_t& r1,
                                       uint32_t& r2, uint32_t& r3) {
    asm volatile("ldmatrix.sync.aligned.m8n8.x4.trans.shared.b16 {%0,%1,%2,%3}, [%4];"
                 : "=r"(r0), "=r"(r1), "=r"(r2), "=r"(r3) : "r"(a));
}
__device__ __forceinline__ void mma16816h(float* d, const uint32_t* a, const uint32_t* b) {
    asm volatile("mma.sync.aligned.m16n8k16.row.col.f32.f16.f16.f32 "
                 "{%0,%1,%2,%3}, {%4,%5,%6,%7}, {%8,%9}, {%0,%1,%2,%3};"
                 : "+f"(d[0]), "+f"(d[1]), "+f"(d[2]), "+f"(d[3])
                 : "r"(a[0]), "r"(a[1]), "r"(a[2]), "r"(a[3]), "r"(b[0]), "r"(b[1]));
}

// ---------------- one-shot weight split (fp16 hi/lo; embed fp16) -------------
#define Q0 (SZ_WQKV/4)
#define Q1 (Q0 + SZ_WO/4)
#define Q2 (Q1 + SZ_WG/4)
#define Q3 (Q2 + SZ_W1/4)
#define Q4 (Q3 + SZ_W2/4)
#define Q5 (Q4 + SZ_EMB/4)
__global__ void split_all(
    const float4* w0, const float4* w1, const float4* w2,
    const float4* w3, const float4* w4, const float4* w5,
    uint2* h0, uint2* l0, uint2* h1, uint2* l1, uint2* h2, uint2* l2,
    uint2* h3, uint2* l3, uint2* h4, uint2* l4, uint2* f5)
{
    long i = (long)blockIdx.x * 256 + threadIdx.x;
    if (i >= Q5) return;
    const float4* src; uint2 *hi, *lo; long off; int single;
    if      (i < Q0) { src = w0; hi = h0; lo = l0; off = i;      single = 0; }
    else if (i < Q1) { src = w1; hi = h1; lo = l1; off = i - Q0; single = 0; }
    else if (i < Q2) { src = w2; hi = h2; lo = l2; off = i - Q1; single = 0; }
    else if (i < Q3) { src = w3; hi = h3; lo = l3; off = i - Q2; single = 0; }
    else if (i < Q4) { src = w4; hi = h4; lo = l4; off = i - Q3; single = 0; }
    else             { src = w5; hi = f5; lo = f5; off = i - Q4; single = 1; }
    float4 v = src[off];
    float vv[4] = {v.x, v.y, v.z, v.w};
    uint32_t Hw[2] = {0, 0}, Lw[2] = {0, 0};
    #pragma unroll
    for (int k = 0; k < 4; k++) {
        __half a = __float2half_rn(vv[k]);
        Hw[k >> 1] |= (uint32_t)__half_as_ushort(a) << ((k & 1) * 16);
        if (!single) {
            __half b = __float2half_rn(vv[k] - __half2float(a));
            Lw[k >> 1] |= (uint32_t)__half_as_ushort(b) << ((k & 1) * 16);
        }
    }
    hi[off] = make_uint2(Hw[0], Hw[1]);
    if (!single) lo[off] = make_uint2(Lw[0], Lw[1]);
}

// ---------------- gemm_hA: BN=128, KC=32, SROW=80, warp 32x64 ----------------
#define SRA   80
#define A_ASZ (128 * SRA)
#define A_BSZ (128 * SRA)
#define A_STG (A_ASZ + 2 * A_BSZ)
#define GHA   (2 * A_STG)

__global__ __launch_bounds__(256, 2) void gemm_hA(
    const __half* __restrict__ A16,
    const __half* __restrict__ Wh, const __half* __restrict__ Wl,
    const float* __restrict__ bias,
    __half* __restrict__ Chh, __half* __restrict__ Chl, __half* __restrict__ C16,
    int M, int N, int K, int epi)
{
    extern __shared__ char smem[];
    uint32_t sb = smem_u32(smem);
    int tid = threadIdx.x, lane = tid & 31, w = tid >> 5;
    int wm = w & 3, wn = w >> 2;
    int bm = blockIdx.y * 128, bn = blockIdx.x * 128;

    float acc[2][8][4];
    #pragma unroll
    for (int i = 0; i < 2; i++)
        #pragma unroll
        for (int j = 0; j < 8; j++)
            #pragma unroll
            for (int e = 0; e < 4; e++) acc[i][j][e] = 0.f;

    int nk = K / 32;

    auto load_chunk = [&](int kc, uint32_t s) {
        int kb = kc * 32;
        #pragma unroll
        for (int it = 0; it < 6; it++) {
            int i = tid + it * 256;
            if (i < 512) {
                int row = i >> 2, c = i & 3;
                size_t go = (size_t)(bm + row) * K + kb + c * 8;
                cp16(s + row * SRA + c * 16, A16 + go);
            } else {
                int ii = i - 512;
                int hf = ii >= 512;
                int ww = ii & 511;
                int row = ww >> 2, c = ww & 3;
                size_t go = (size_t)(bn + row) * K + kb + c * 8;
                cp16(s + A_ASZ + (hf ? A_BSZ : 0) + row * SRA + c * 16, (hf ? Wl : Wh) + go);
            }
        }
    };

    load_chunk(0, sb);
    CP_COMMIT();

    for (int kc = 0; kc < nk; kc++) {
        CP_WAIT0();
        __syncthreads();
        if (kc + 1 < nk) { load_chunk(kc + 1, sb + ((kc + 1) & 1) * A_STG); CP_COMMIT(); }

        uint32_t s = sb + (kc & 1) * A_STG;
        #pragma unroll
        for (int t = 0; t < 2; t++) {
            uint32_t arow = wm * 32 + (lane & 15);
            uint32_t ak = (t * 16 + (lane >> 4) * 8) * 2;
            uint32_t ar[2][4];
            #pragma unroll
            for (int mg = 0; mg < 2; mg++) {
                uint32_t aoff = (arow + mg * 16) * SRA + ak;
                ldmx4(s + aoff, ar[mg][0], ar[mg][1], ar[mg][2], ar[mg][3]);
            }
            #pragma unroll
            for (int ng = 0; ng < 4; ng++) {
                uint32_t brow = wn * 64 + ng * 16 + (lane & 7) + ((lane >> 4) << 3);
                uint32_t boff = brow * SRA + (t * 16 + ((lane >> 3) & 1) * 8) * 2;
                uint32_t bh[4], bl[4];
                ldmx4(s + A_ASZ + boff,         bh[0], bh[1], bh[2], bh[3]);
                ldmx4(s + A_ASZ + A_BSZ + boff, bl[0], bl[1], bl[2], bl[3]);
                #pragma unroll
                for (int mg = 0; mg < 2; mg++) {
                    mma16816h(acc[mg][ng*2+0], ar[mg], &bh[0]);
                    mma16816h(acc[mg][ng*2+1], ar[mg], &bh[2]);
                    mma16816h(acc[mg][ng*2+0], ar[mg], &bl[0]);
                    mma16816h(acc[mg][ng*2+1], ar[mg], &bl[2]);
                }
            }
        }
    }

    #pragma unroll
    for (int mg = 0; mg < 2; mg++) {
        #pragma unroll
        for (int j = 0; j < 8; j++) {
            int m0 = bm + wm * 32 + mg * 16 + (lane >> 2);
            int n0 = bn + wn * 64 + j * 8 + (lane & 3) * 2;
            #pragma unroll
            for (int e = 0; e < 4; e++) {
                int m = m0 + (e >> 1) * 8;
                int n = n0 + (e & 1);
                size_t idx = (size_t)m * N + n;
                float v = acc[mg][j][e];
                if (bias) v += bias[n];
                if (epi == 2) v = 0.5f * v * (1.f + erff(v * 0.70710678118f));
                if (Chh) {
                    __half a = __float2half_rn(v);
                    Chh[idx] = a;
                    Chl[idx] = __float2half_rn(v - __half2float(a));
                }
                if (C16) C16[idx] = __float2half_rn(v);
            }
        }
    }
}

// ---------------- gemm_hB: BN=64, KC=64, SR=144, warp 32x32 ------------------
#define SRB   144
#define B_ASZ (128 * SRB)
#define B_BSZ (64 * SRB)
#define B_STG (B_ASZ + 2 * B_BSZ)
#define GHB   (2 * B_STG)

__global__ __launch_bounds__(256, 2) void gemm_hB(
    const __half* __restrict__ A16, const __half* __restrict__ A16b,
    int kSplit, int lda1, int lda2,
    const __half* __restrict__ Wh, const __half* __restrict__ Wl,
    const float* __restrict__ bias, const float* __restrict__ res,
    const float* __restrict__ corr,
    float* __restrict__ Cf, __half* __restrict__ C16,
    int M, int N, int K, int epi)
{
    extern __shared__ char smem[];
    uint32_t sb = smem_u32(smem);
    int tid = threadIdx.x, lane = tid & 31, w = tid >> 5;
    int wm = w & 3, wn = w >> 2;
    int bm = blockIdx.y * 128, bn = blockIdx.x * 64;

    float acc[2][4][4];
    #pragma unroll
    for (int i = 0; i < 2; i++)
        #pragma unroll
        for (int j = 0; j < 4; j++)
            #pragma unroll
            for (int e = 0; e < 4; e++) acc[i][j][e] = 0.f;

    int nk = K / 64;

    auto load_chunk = [&](int kc, uint32_t s) {
        int kb = kc * 64;
        const __half* sA; int lda, koff;
        if (kb < kSplit) { sA = A16;  lda = lda1; koff = kb; }
        else             { sA = A16b; lda = lda2; koff = kb - kSplit; }
        #pragma unroll
        for (int it = 0; it < 8; it++) {
            int i = tid + it * 256;
            if (i < 1024) {
                int row = i >> 3, c = i & 7;
                size_t go = (size_t)(bm + row) * lda + koff + c * 8;
                cp16(s + row * SRB + c * 16, sA + go);
            } else {
                int ii = i - 1024;
                int hf = ii >= 512;
                int ww = ii & 511;
                int row = ww >> 3, c = ww & 7;
                size_t go = (size_t)(bn + row) * K + kb + c * 8;
                cp16(s + B_ASZ + (hf ? B_BSZ : 0) + row * SRB + c * 16, (hf ? Wl : Wh) + go);
            }
        }
    };

    load_chunk(0, sb);
    CP_COMMIT();

    for (int kc = 0; kc < nk; kc++) {
        CP_WAIT0();
        __syncthreads();
        if (kc + 1 < nk) { load_chunk(kc + 1, sb + ((kc + 1) & 1) * B_STG); CP_COMMIT(); }

        uint32_t s = sb + (kc & 1) * B_STG;
        #pragma unroll
        for (int t = 0; t < 4; t++) {
            uint32_t arow = wm * 32 + (lane & 15);
            uint32_t ak = (t * 16 + (lane >> 4) * 8) * 2;
            uint32_t ar[2][4];
            #pragma unroll
            for (int mg = 0; mg < 2; mg++) {
                uint32_t aoff = (arow + mg * 16) * SRB + ak;
                ldmx4(s + aoff, ar[mg][0], ar[mg][1], ar[mg][2], ar[mg][3]);
            }
            #pragma unroll
            for (int ng = 0; ng < 2; ng++) {
                uint32_t brow = wn * 32 + ng * 16 + (lane & 7) + ((lane >> 4) << 3);
                uint32_t boff = brow * SRB + (t * 16 + ((lane >> 3) & 1) * 8) * 2;
                uint32_t bh[4], bl[4];
                ldmx4(s + B_ASZ + boff,         bh[0], bh[1], bh[2], bh[3]);
                ldmx4(s + B_ASZ + B_BSZ + boff, bl[0], bl[1], bl[2], bl[3]);
                #pragma unroll
                for (int mg = 0; mg < 2; mg++) {
                    mma16816h(acc[mg][ng*2+0], ar[mg], &bh[0]);
                    mma16816h(acc[mg][ng*2+1], ar[mg], &bh[2]);
                    mma16816h(acc[mg][ng*2+0], ar[mg], &bl[0]);
                    mma16816h(acc[mg][ng*2+1], ar[mg], &bl[2]);
                }
            }
        }
    }

    #pragma unroll
    for (int mg = 0; mg < 2; mg++) {
        #pragma unroll
        for (int j = 0; j < 4; j++) {
            int m0 = bm + wm * 32 + mg * 16 + (lane >> 2);
            int n0 = bn + wn * 32 + j * 8 + (lane & 3) * 2;
            #pragma unroll
            for (int e = 0; e < 4; e++) {
                int m = m0 + (e >> 1) * 8;
                int n = n0 + (e & 1);
                size_t idx = (size_t)m * N + n;
                float v = acc[mg][j][e];
                if (bias) v += bias[n];
                if (epi == 1)      v += res[idx];
                else if (epi == 3) v = res[idx] + corr[idx] / (1.f + __expf(-v));
                if (Cf) Cf[idx] = v;
                if (C16) C16[idx] = __float2half_rn(v);
            }
        }
    }
}

// ---------------- logits GEMM (fp16 1-mma, 128x64, KC=64) --------------------
#define FB    (128 * SRB)
#define FSTG  (FB + 64 * SRB)
#define FSMEM (2 * FSTG)

__global__ __launch_bounds__(256, 3) void gemm_f16(
    const __half* __restrict__ Ah, const __half* __restrict__ Wh,
    float* __restrict__ Cf, int M, int N, int K)
{
    extern __shared__ char smem[];
    uint32_t sb = smem_u32(smem);
    int tid = threadIdx.x, lane = tid & 31, w = tid >> 5;
    int wm = w & 3, wn = w >> 2;
    int bm = blockIdx.y * 128, bn = blockIdx.x * 64;

    float acc[2][4][4];
    #pragma unroll
    for (int i = 0; i < 2; i++)
        #pragma unroll
        for (int j = 0; j < 4; j++)
            #pragma unroll
            for (int e = 0; e < 4; e++) acc[i][j][e] = 0.f;

    int nk = K / 64;

    auto load_chunk = [&](int kc, uint32_t s) {
        int kb = kc * 64;
        #pragma unroll
        for (int it = 0; it < 6; it++) {
            int i = tid + it * 256;
            if (i < 1024) {
                int row = i >> 3, c = i & 7;
                size_t go = (size_t)(bm + row) * K + kb + c * 8;
                cp16(s + row * SRB + c * 16, Ah + go);
            } else {
                int ii = i - 1024;
                int row = ii >> 3, c = ii & 7;
                size_t go = (size_t)(bn + row) * K + kb + c * 8;
                cp16(s + FB + row * SRB + c * 16, Wh + go);
            }
        }
    };

    load_chunk(0, sb);
    CP_COMMIT();

    for (int kc = 0; kc < nk; kc++) {
        CP_WAIT0();
        __syncthreads();
        if (kc + 1 < nk) { load_chunk(kc + 1, sb + ((kc + 1) & 1) * FSTG); CP_COMMIT(); }

        uint32_t s = sb + (kc & 1) * FSTG;
        #pragma unroll
        for (int t = 0; t < 4; t++) {
            uint32_t arow = wm * 32 + (lane & 15);
            uint32_t ak = (t * 16 + (lane >> 4) * 8) * 2;
            uint32_t ahr[2][4];
            #pragma unroll
            for (int mg = 0; mg < 2; mg++) {
                uint32_t aoff = (arow + mg * 16) * SRB + ak;
                ldmx4(s + aoff, ahr[mg][0], ahr[mg][1], ahr[mg][2], ahr[mg][3]);
            }
            #pragma unroll
            for (int ng = 0; ng < 2; ng++) {
                uint32_t brow = wn * 32 + ng * 16 + (lane & 7) + ((lane >> 4) << 3);
                uint32_t boff = brow * SRB + (t * 16 + ((lane >> 3) & 1) * 8) * 2;
                uint32_t bw[4];
                ldmx4(s + FB + boff, bw[0], bw[1], bw[2], bw[3]);
                #pragma unroll
                for (int mg = 0; mg < 2; mg++) {
                    mma16816h(acc[mg][ng*2+0], ahr[mg], &bw[0]);
                    mma16816h(acc[mg][ng*2+1], ahr[mg], &bw[2]);
                }
            }
        }
    }

    #pragma unroll
    for (int mg = 0; mg < 2; mg++) {
        #pragma unroll
        for (int j = 0; j < 4; j++) {
            int m0 = bm + wm * 32 + mg * 16 + (lane >> 2);
            int n0 = bn + wn * 32 + j * 8 + (lane & 3) * 2;
            #pragma unroll
            for (int e = 0; e < 4; e++) {
                int m = m0 + (e >> 1) * 8;
                int n = n0 + (e & 1);
                Cf[(size_t)m * N + n] = acc[mg][j][e];
            }
        }
    }
}

// ---------------- embedding ------------------------------------------------
__global__ void embed_kernel(const int* __restrict__ x, const float* __restrict__ emb,
                             const float* __restrict__ pos, float* __restrict__ h) {
    int row = blockIdx.x;
    int t   = row & (T_SEQ - 1);
    int tok = x[row];
    const float* e = emb + (size_t)tok * D_MODEL;
    const float* p = pos + (size_t)t   * D_MODEL;
    float* o = h + (size_t)row * D_MODEL;
    for (int d = threadIdx.x; d < D_MODEL; d += blockDim.x)
        o[d] = e[d] + p[d];
}

// ---------------- layernorm -------------------------------------------------
__global__ void ln_kernel(const float* __restrict__ in, const float* __restrict__ g,
                          const float* __restrict__ b, float* __restrict__ of,
                          __half* __restrict__ o16) {
    int row = blockIdx.x;
    const float* x = in + (size_t)row * D_MODEL;
    int tid = threadIdx.x;
    float s = 0.f, ss = 0.f;
    for (int d = tid; d < D_MODEL; d += 256) { float v = x[d]; s += v; ss += v * v; }
    #pragma unroll
    for (int off = 16; off; off >>= 1) {
        s  += __shfl_xor_sync(0xffffffffu, s,  off);
        ss += __shfl_xor_sync(0xffffffffu, ss, off);
    }
    __shared__ float shs[8], shss[8];
    if ((tid & 31) == 0) { shs[tid >> 5] = s; shss[tid >> 5] = ss; }
    __syncthreads();
    float tots = 0.f, totss = 0.f;
    #pragma unroll
    for (int i = 0; i < 8; i++) { tots += shs[i]; totss += shss[i]; }
    float mean = tots * (1.f / D_MODEL);
    float var  = totss * (1.f / D_MODEL) - mean * mean;
    float rstd = rsqrtf(var + 1e-5f);
    for (int d = tid; d < D_MODEL; d += 256) {
        float v = (x[d] - mean) * rstd * g[d] + b[d];
        size_t idx = (size_t)row * D_MODEL + d;
        if (of) of[idx] = v;
        o16[idx] = __float2half_rn(v);
    }
}

// ---------------- HMMA flash attention (fp16, Q/P single, K/V hi-lo) ---------
#define AT_ROWB   144
#define AT_Q      0
#define AT_STAGE0 9216
#define AT_STGSZ  36864
#define AT_KH     0
#define AT_KL     9216
#define AT_VH     18432
#define AT_VL     27648
#define AT_SMEM   (9216 + 2 * 36864)

__global__ __launch_bounds__(128, 2) void attn_mma(
    const __half* __restrict__ qkvh, const __half* __restrict__ qkvl,
    const float* __restrict__ nIn,
    float* __restrict__ outF, __half* __restrict__ o16, __half* __restrict__ d16)
{
    extern __shared__ char sm[];
    uint32_t sb = smem_u32(sm);
    int qt = blockIdx.x, hh = blockIdx.y, b = blockIdx.z;
    int tid = threadIdx.x, lane = tid & 31, wq = tid >> 5;
    int qb = wq * 16;

    #pragma unroll
    for (int it = 0; it < 4; it++) {
        int i = tid + it * 128;
        int row = i >> 3, c = i & 7;
        size_t ge = (size_t)(b * T_SEQ + qt * 64 + row) * 3072 + hh * 64 + c * 8;
        cp16(sb + AT_Q + row * AT_ROWB + c * 16, qkvh + ge);
    }

    auto load_kv = [&](int kt, int stage) {
        uint32_t stb = sb + AT_STAGE0 + stage * AT_STGSZ;
        #pragma unroll
        for (int it = 0; it < 16; it++) {
            int i = tid + it * 128;
            int tensor = i >> 9, ww = i & 511, row = ww >> 3, c = ww & 7;
            int kvoff = (tensor >= 2) ? 2048 : 1024;
            size_t ge = (size_t)(b * T_SEQ + kt * 64 + row) * 3072 + kvoff + hh * 64 + c * 8;
            const __half* src = (tensor & 1) ? qkvl : qkvh;
            uint32_t toff = tensor * 9216;
            cp16(stb + toff + row * AT_ROWB + c * 16, src + ge);
        }
    };
    load_kv(0, 0);
    CP_COMMIT();

    float O[8][4];
    #pragma unroll
    for (int j = 0; j < 8; j++)
        #pragma unroll
        for (int e = 0; e < 4; e++) O[j][e] = 0.f;
    float m0 = -1e30f, m1 = -1e30f, l0 = 0.f, l1 = 0.f;

    int r0 = qt * 64 + qb + (lane >> 2);
    int r1 = r0 + 8;

    for (int kt = 0; kt <= qt; kt++) {
        CP_WAIT0();
        __syncthreads();
        if (kt < qt) { load_kv(kt + 1, (kt + 1) & 1); CP_COMMIT(); }

        uint32_t stb = sb + AT_STAGE0 + (kt & 1) * AT_STGSZ;

        float S[8][4];
        #pragma unroll
        for (int j = 0; j < 8; j++)
            #pragma unroll
            for (int e = 0; e < 4; e++) S[j][e] = 0.f;

        #pragma unroll
        for (int t = 0; t < 4; t++) {
            uint32_t qa = sb + AT_Q + (qb + (lane & 15)) * AT_ROWB + (t * 16 + (lane >> 4) * 8) * 2;
            uint32_t q[4];
            ldmx4(qa, q[0], q[1], q[2], q[3]);
            #pragma unroll
            for (int jj = 0; jj < 4; jj++) {
                uint32_t ka = stb + (jj * 16 + (lane & 7) + ((lane >> 4) << 3)) * AT_ROWB
                            + (t * 16 + ((lane >> 3) & 1) * 8) * 2;
                uint32_t kh[4], kl[4];
                ldmx4(ka + AT_KH, kh[0], kh[1], kh[2], kh[3]);
                ldmx4(ka + AT_KL, kl[0], kl[1], kl[2], kl[3]);
                mma16816h(S[jj*2+0], q, &kh[0]); mma16816h(S[jj*2+1], q, &kh[2]);
                mma16816h(S[jj*2+0], q, &kl[0]); mma16816h(S[jj*2+1], q, &kl[2]);
            }
        }

        int cb = kt * 64 + ((lane & 3) << 1);
        float mx0 = -1e30f, mx1 = -1e30f;
        #pragma unroll
        for (int j = 0; j < 8; j++) {
            int c0 = cb + j * 8, c1 = c0 + 1;
            float v;
            v = (c0 <= r0) ? S[j][0] * ATT_SCALE : -1e30f; S[j][0] = v; mx0 = fmaxf(mx0, v);
            v = (c1 <= r0) ? S[j][1] * ATT_SCALE : -1e30f; S[j][1] = v; mx0 = fmaxf(mx0, v);
            v = (c0 <= r1) ? S[j][2] * ATT_SCALE : -1e30f; S[j][2] = v; mx1 = fmaxf(mx1, v);
            v = (c1 <= r1) ? S[j][3] * ATT_SCALE : -1e30f; S[j][3] = v; mx1 = fmaxf(mx1, v);
        }
        mx0 = fmaxf(mx0, __shfl_xor_sync(0xffffffffu, mx0, 1));
        mx0 = fmaxf(mx0, __shfl_xor_sync(0xffffffffu, mx0, 2));
        mx1 = fmaxf(mx1, __shfl_xor_sync(0xffffffffu, mx1, 1));
        mx1 = fmaxf(mx1, __shfl_xor_sync(0xffffffffu, mx1, 2));
        float mn0 = fmaxf(m0, mx0), mn1 = fmaxf(m1, mx1);
        float a0 = __expf(m0 - mn0), a1 = __expf(m1 - mn1);
        m0 = mn0; m1 = mn1;
        float s0 = 0.f, s1 = 0.f;
        #pragma unroll
        for (int j = 0; j < 8; j++) {
            S[j][0] = __expf(S[j][0] - m0); s0 += S[j][0];
            S[j][1] = __expf(S[j][1] - m0); s0 += S[j][1];
            S[j][2] = __expf(S[j][2] - m1); s1 += S[j][2];
            S[j][3] = __expf(S[j][3] - m1); s1 += S[j][3];
        }
        s0 += __shfl_xor_sync(0xffffffffu, s0, 1);
        s0 += __shfl_xor_sync(0xffffffffu, s0, 2);
        s1 += __shfl_xor_sync(0xffffffffu, s1, 1);
        s1 += __shfl_xor_sync(0xffffffffu, s1, 2);
        l0 = l0 * a0 + s0; l1 = l1 * a1 + s1;
        #pragma unroll
        for (int j = 0; j < 8; j++) {
            O[j][0] *= a0; O[j][1] *= a0; O[j][2] *= a1; O[j][3] *= a1;
        }

        #pragma unroll
        for (int t = 0; t < 4; t++) {
            uint32_t pa[4];
            pa[0] = packh(S[2*t  ][0], S[2*t  ][1]);
            pa[1] = packh(S[2*t  ][2], S[2*t  ][3]);
            pa[2] = packh(S[2*t+1][0], S[2*t+1][1]);
            pa[3] = packh(S[2*t+1][2], S[2*t+1][3]);
            #pragma unroll
            for (int dd = 0; dd < 4; dd++) {
                uint32_t va = stb + (t * 16 + (lane & 7) + ((lane >> 3) & 1) * 8) * AT_ROWB
                            + (dd * 16 + (lane >> 4) * 8) * 2;
                uint32_t vh[4], vl[4];
                ldmx4t(va + AT_VH, vh[0], vh[1], vh[2], vh[3]);
                ldmx4t(va + AT_VL, vl[0], vl[1], vl[2], vl[3]);
                mma16816h(O[dd*2+0], pa, &vh[0]); mma16816h(O[dd*2+1], pa, &vh[2]);
                mma16816h(O[dd*2+0], pa, &vl[0]); mma16816h(O[dd*2+1], pa, &vl[2]);
            }
        }
    }

    float i0 = 1.f / l0, i1 = 1.f / l1;
    int tok0 = b * T_SEQ + r0, tok1 = b * T_SEQ + r1;
    #pragma unroll
    for (int j = 0; j < 8; j++) {
        int d = hh * 64 + j * 8 + ((lane & 3) << 1);
        size_t idx0 = (size_t)tok0 * D_MODEL + d;
        size_t idx1 = (size_t)tok1 * D_MODEL + d;
        float v00 = O[j][0] * i0, v01 = O[j][1] * i0;
        float v10 = O[j][2] * i1, v11 = O[j][3] * i1;
        outF[idx0] = v00; outF[idx0 + 1] = v01;
        outF[idx1] = v10; outF[idx1 + 1] = v11;
        o16[idx0]     = __float2half_rn(v00);
        o16[idx0 + 1] = __float2half_rn(v01);
        o16[idx1]     = __float2half_rn(v10);
        o16[idx1 + 1] = __float2half_rn(v11);
        if (d16) {
            d16[idx0]     = __float2half_rn(nIn[idx0]     - v00);
            d16[idx0 + 1] = __float2half_rn(nIn[idx0 + 1] - v01);
            d16[idx1]     = __float2half_rn(nIn[idx1]     - v10);
            d16[idx1 + 1] = __float2half_rn(nIn[idx1 + 1] - v11);
        }
    }
}

// ---------------- driver ----------------------------------------------------
extern "C" void kernel_launch(void* const* d_in, const int* in_sizes, int n_in,
                              void* d_out, int out_size) {
    const int*   x      = (const int*)  d_in[0];
    const float* embed  = (const float*)d_in[1];
    const float* pos    = (const float*)d_in[2];
    const float* Wqkv   = (const float*)d_in[3];
    const float* bqkv   = (const float*)d_in[4];
    const float* Wo     = (const float*)d_in[5];
    const float* bo     = (const float*)d_in[6];
    const float* Wg     = (const float*)d_in[7];
    const float* bg     = (const float*)d_in[8];
    const float* ln1_g  = (const float*)d_in[9];
    const float* ln1_b  = (const float*)d_in[10];
    const float* W1     = (const float*)d_in[11];
    const float* b1     = (const float*)d_in[12];
    const float* W2     = (const float*)d_in[13];
    const float* b2     = (const float*)d_in[14];
    const float* ln2_g  = (const float*)d_in[15];
    const float* ln2_b  = (const float*)d_in[16];
    const float* lnf_g  = (const float*)d_in[17];
    const float* lnf_b  = (const float*)d_in[18];
    float* out = (float*)d_out;

    cudaFuncSetAttribute(gemm_hA,  cudaFuncAttributeMaxDynamicSharedMemorySize, GHA);
    cudaFuncSetAttribute(gemm_hB,  cudaFuncAttributeMaxDynamicSharedMemorySize, GHB);
    cudaFuncSetAttribute(gemm_f16, cudaFuncAttributeMaxDynamicSharedMemorySize, FSMEM);
    cudaFuncSetAttribute(attn_mma, cudaFuncAttributeMaxDynamicSharedMemorySize, AT_SMEM);

    float *h, *n, *pred, *corr;
    cudaGetSymbolAddress((void**)&h,    g_h);
    cudaGetSymbolAddress((void**)&n,    g_n);
    cudaGetSymbolAddress((void**)&pred, g_pred);
    cudaGetSymbolAddress((void**)&corr, g_corr);
    __half *qh, *ql, *a16, *d16, *p16, *c16, *gg16, *f16, *embf;
    cudaGetSymbolAddress((void**)&qh,   g_qkvh);
    cudaGetSymbolAddress((void**)&ql,   g_qkvl);
    cudaGetSymbolAddress((void**)&a16,  g_a16);
    cudaGetSymbolAddress((void**)&d16,  g_d16);
    cudaGetSymbolAddress((void**)&p16,  g_p16);
    cudaGetSymbolAddress((void**)&c16,  g_c16);
    cudaGetSymbolAddress((void**)&gg16, g_g16);
    cudaGetSymbolAddress((void**)&f16,  g_f16);
    cudaGetSymbolAddress((void**)&embf, g_embf);
    __half *wqkv_h, *wqkv_l, *wo_h, *wo_l, *wg_h, *wg_l, *w1_h, *w1_l, *w2_h, *w2_l;
    cudaGetSymbolAddress((void**)&wqkv_h, g_wqkv_h); cudaGetSymbolAddress((void**)&wqkv_l, g_wqkv_l);
    cudaGetSymbolAddress((void**)&wo_h,   g_wo_h);   cudaGetSymbolAddress((void**)&wo_l,   g_wo_l);
    cudaGetSymbolAddress((void**)&wg_h,   g_wg_h);   cudaGetSymbolAddress((void**)&wg_l,   g_wg_l);
    cudaGetSymbolAddress((void**)&w1_h,   g_w1_h);   cudaGetSymbolAddress((void**)&w1_l,   g_w1_l);
    cudaGetSymbolAddress((void**)&w2_h,   g_w2_h);   cudaGetSymbolAddress((void**)&w2_l,   g_w2_l);

    split_all<<<(int)((Q5 + 255) / 256), 256>>>(
        (const float4*)Wqkv, (const float4*)Wo, (const float4*)Wg,
        (const float4*)W1, (const float4*)W2, (const float4*)embed,
        (uint2*)wqkv_h, (uint2*)wqkv_l, (uint2*)wo_h, (uint2*)wo_l,
        (uint2*)wg_h, (uint2*)wg_l, (uint2*)w1_h, (uint2*)w1_l,
        (uint2*)w2_h, (uint2*)w2_l, (uint2*)embf);

    dim3 attng(T_SEQ / 64, 16, 2);

    embed_kernel<<<BT, 256>>>(x, embed, pos, h);

    for (int l = 0; l < NLAYER; l++) {
        ln_kernel<<<BT, 256>>>(h, ln1_g + l * D_MODEL, ln1_b + l * D_MODEL, n, a16);
        gemm_hA<<<dim3(3072/128, BT/128), 256, GHA>>>(
            a16, wqkv_h + (size_t)(l*2+0)*3072*D_MODEL, wqkv_l + (size_t)(l*2+0)*3072*D_MODEL,
            bqkv + (l*2+0)*3072, qh, ql, nullptr, BT, 3072, D_MODEL, 0);
        attn_mma<<<attng, 128, AT_SMEM>>>(qh, ql, n, pred, p16, d16);
        gemm_hA<<<dim3(3072/128, BT/128), 256, GHA>>>(
            d16, wqkv_h + (size_t)(l*2+1)*3072*D_MODEL, wqkv_l + (size_t)(l*2+1)*3072*D_MODEL,
            bqkv + (l*2+1)*3072, qh, ql, nullptr, BT, 3072, D_MODEL, 0);
        attn_mma<<<attng, 128, AT_SMEM>>>(qh, ql, nullptr, corr, c16, nullptr);
        gemm_hB<<<dim3(D_MODEL/64, BT/128), 256, GHB>>>(
            p16, c16, D_MODEL, D_MODEL, D_MODEL,
            wg_h + (size_t)l*D_MODEL*2*D_MODEL, wg_l + (size_t)l*D_MODEL*2*D_MODEL,
            bg + l*D_MODEL, pred, corr,
            nullptr, gg16, BT, D_MODEL, 2*D_MODEL, 3);
        gemm_hB<<<dim3(D_MODEL/64, BT/128), 256, GHB>>>(
            gg16, nullptr, 1 << 30, D_MODEL, 0,
            wo_h + (size_t)l*D_MODEL*D_MODEL, wo_l + (size_t)l*D_MODEL*D_MODEL,
            bo + l*D_MODEL, h, nullptr,
            h, nullptr, BT, D_MODEL, D_MODEL, 1);
        ln_kernel<<<BT, 256>>>(h, ln2_g + l * D_MODEL, ln2_b + l * D_MODEL, nullptr, a16);
        gemm_hA<<<dim3(FF_DIM/128, BT/128), 256, GHA>>>(
            a16, w1_h + (size_t)l*FF_DIM*D_MODEL, w1_l + (size_t)l*FF_DIM*D_MODEL,
            b1 + l*FF_DIM, nullptr, nullptr, f16, BT, FF_DIM, D_MODEL, 2);
        gemm_hB<<<dim3(D_MODEL/64, BT/128), 256, GHB>>>(
            f16, nullptr, 1 << 30, FF_DIM, 0,
            w2_h + (size_t)l*D_MODEL*FF_DIM, w2_l + (size_t)l*D_MODEL*FF_DIM,
            b2 + l*D_MODEL, h, nullptr,
            h, nullptr, BT, D_MODEL, FF_DIM, 1);
    }

    ln_kernel<<<BT, 256>>>(h, lnf_g, lnf_b, nullptr, a16);
    gemm_f16<<<dim3(VOCAB/64, BT/128), 256, FSMEM>>>(
        a16, embf, out, BT, VOCAB, D_MODEL);
}